// round 1
// baseline (speedup 1.0000x reference)
#include <cuda_runtime.h>

// Problem dims (fixed by the reference): B=4, S=4096, D=4096, E=64, K=2
#define NTOK 16384          // B*S tokens
#define DDIM 4096
#define NEXP 64

// GEMM tiling
#define TB 64               // tokens per CTA
#define DC 32               // D-chunk per iteration

// Output layout (tuple order, flattened to float32):
// idx[NTOK*2], scores[NTOK*2], probs[NTOK*64], z_loss[1], importance[64], load[64]
#define OFF_IDX     0
#define OFF_SCORES  (NTOK * 2)
#define OFF_PROBS   (NTOK * 4)
#define OFF_ZLOSS   (NTOK * 4 + NTOK * NEXP)
#define OFF_IMP     (OFF_ZLOSS + 1)
#define OFF_LOAD    (OFF_IMP + NEXP)

// Scratch (allocation-free rule: __device__ globals)
__device__ float g_Wt[DDIM * NEXP];          // W transposed: [k][e]
__device__ float g_logits[(size_t)NTOK * NEXP];
__device__ float g_acc[2 * NEXP + 1];        // [0:64) importance, [64:128) counts, [128] z*z sum

// ---------------------------------------------------------------------------
// packed f32x2 helpers (fma.rn.f32x2 is PTX-only on sm_103a; ptxas won't fuse)
// ---------------------------------------------------------------------------
__device__ __forceinline__ unsigned long long pack_dup(float v) {
    unsigned long long r;
    asm("mov.b64 %0, {%1, %1};" : "=l"(r) : "f"(v));
    return r;
}
__device__ __forceinline__ void ffma2(unsigned long long& c,
                                      unsigned long long a,
                                      unsigned long long b) {
    asm("fma.rn.f32x2 %0, %1, %2, %0;" : "+l"(c) : "l"(a), "l"(b));
}
__device__ __forceinline__ float2 unpk(unsigned long long v) {
    float2 f;
    asm("mov.b64 {%0, %1}, %2;" : "=f"(f.x), "=f"(f.y) : "l"(v));
    return f;
}

// ---------------------------------------------------------------------------
// Kernel 1: transpose W [E][D] -> Wt [D][E], and zero the accumulators
// ---------------------------------------------------------------------------
__global__ void prep_kernel(const float* __restrict__ W) {
    int idx = blockIdx.x * 256 + threadIdx.x;
    if (idx < DDIM * NEXP) {
        int e = idx / DDIM;
        int k = idx - e * DDIM;     // consecutive threads -> consecutive k: coalesced read
        g_Wt[k * NEXP + e] = W[idx];
    }
    if (blockIdx.x == 0 && threadIdx.x < 2 * NEXP + 1) g_acc[threadIdx.x] = 0.0f;
}

// ---------------------------------------------------------------------------
// Kernel 2: logits = x @ W^T  (fp32 accumulate via packed f32x2 FMA)
// CTA: 64 tokens x 64 experts, 128 threads.
// Thread tile: 8 tokens (4 packed pairs) x 4 experts.
// tg = tid>>4 (token group, 8 tokens), eg = tid&15 (expert group, 4 experts)
// ---------------------------------------------------------------------------
__global__ __launch_bounds__(128) void gemm_kernel(const float* __restrict__ x) {
    __shared__ __align__(16) float Xs[DC][TB + 4];   // [k][t], +4 pad kills STS conflicts
    __shared__ __align__(16) float Ws[DC][NEXP];     // [k][e]

    const int tid = threadIdx.x;
    const int token0 = blockIdx.x * TB;
    const int tg = tid >> 4;     // 0..7  -> tokens tg*8 .. tg*8+7
    const int eg = tid & 15;     // 0..15 -> experts eg*4 .. eg*4+3

    unsigned long long acc[4][4];  // [token-pair][expert]
#pragma unroll
    for (int a = 0; a < 4; a++)
#pragma unroll
        for (int b = 0; b < 4; b++) acc[a][b] = 0ull;

    const float* xg = x + (size_t)token0 * DDIM;

    for (int k0 = 0; k0 < DDIM; k0 += DC) {
        // Load X chunk: 64 rows x 32 k = 512 float4; 4 per thread, coalesced 128B/row
#pragma unroll
        for (int i = 0; i < 4; i++) {
            int q = tid + i * 128;
            int r = q >> 3, c = q & 7;
            float4 v = *reinterpret_cast<const float4*>(xg + (size_t)r * DDIM + k0 + c * 4);
            Xs[c * 4 + 0][r] = v.x;
            Xs[c * 4 + 1][r] = v.y;
            Xs[c * 4 + 2][r] = v.z;
            Xs[c * 4 + 3][r] = v.w;
        }
        // Load W chunk: 32 x 64 = 2048 contiguous floats in g_Wt
#pragma unroll
        for (int i = 0; i < 4; i++) {
            int q = tid + i * 128;
            reinterpret_cast<float4*>(&Ws[0][0])[q] =
                reinterpret_cast<const float4*>(g_Wt + (size_t)k0 * NEXP)[q];
        }
        __syncthreads();

#pragma unroll
        for (int k = 0; k < DC; k++) {
            // token pairs come pre-packed straight out of smem (no movs needed)
            ulonglong2 xa = *reinterpret_cast<const ulonglong2*>(&Xs[k][tg * 8]);
            ulonglong2 xb = *reinterpret_cast<const ulonglong2*>(&Xs[k][tg * 8 + 4]);
            float4 wv = *reinterpret_cast<const float4*>(&Ws[k][eg * 4]);
            unsigned long long w0 = pack_dup(wv.x);
            unsigned long long w1 = pack_dup(wv.y);
            unsigned long long w2 = pack_dup(wv.z);
            unsigned long long w3 = pack_dup(wv.w);

            ffma2(acc[0][0], xa.x, w0); ffma2(acc[0][1], xa.x, w1);
            ffma2(acc[0][2], xa.x, w2); ffma2(acc[0][3], xa.x, w3);
            ffma2(acc[1][0], xa.y, w0); ffma2(acc[1][1], xa.y, w1);
            ffma2(acc[1][2], xa.y, w2); ffma2(acc[1][3], xa.y, w3);
            ffma2(acc[2][0], xb.x, w0); ffma2(acc[2][1], xb.x, w1);
            ffma2(acc[2][2], xb.x, w2); ffma2(acc[2][3], xb.x, w3);
            ffma2(acc[3][0], xb.y, w0); ffma2(acc[3][1], xb.y, w1);
            ffma2(acc[3][2], xb.y, w2); ffma2(acc[3][3], xb.y, w3);
        }
        __syncthreads();
    }

    // Write logits: 8 tokens x 4 experts per thread, float4 stores
#pragma unroll
    for (int tp = 0; tp < 4; tp++) {
        float2 c0 = unpk(acc[tp][0]);
        float2 c1 = unpk(acc[tp][1]);
        float2 c2 = unpk(acc[tp][2]);
        float2 c3 = unpk(acc[tp][3]);
        int t_lo = token0 + tg * 8 + tp * 2;
        float4 lo = make_float4(c0.x, c1.x, c2.x, c3.x);
        float4 hi = make_float4(c0.y, c1.y, c2.y, c3.y);
        *reinterpret_cast<float4*>(g_logits + (size_t)t_lo * NEXP + eg * 4) = lo;
        *reinterpret_cast<float4*>(g_logits + (size_t)(t_lo + 1) * NEXP + eg * 4) = hi;
    }
}

// ---------------------------------------------------------------------------
// Kernel 3: per-token epilogue. One warp per token (lane owns 2 experts).
// Softmax-64, top-2 (ties -> lowest index, matching lax.top_k), pair softmax,
// z^2, plus per-CTA partials for importance / counts / z-loss.
// ---------------------------------------------------------------------------
__device__ __forceinline__ bool better(float v1, int i1, float v2, int i2) {
    return (v1 > v2) || (v1 == v2 && i1 < i2);
}

__global__ __launch_bounds__(256) void epilogue_kernel(float* __restrict__ out) {
    __shared__ float s_imp[NEXP];
    __shared__ float s_cnt[NEXP];
    __shared__ float s_z;
    const int tid = threadIdx.x;
    if (tid < NEXP) { s_imp[tid] = 0.0f; s_cnt[tid] = 0.0f; }
    if (tid == 0) s_z = 0.0f;
    __syncthreads();

    const int warp = tid >> 5, lane = tid & 31;
    const int token = blockIdx.x * 8 + warp;

    const float2 v = reinterpret_cast<const float2*>(g_logits + (size_t)token * NEXP)[lane];

    // max over 64
    float m = fmaxf(v.x, v.y);
#pragma unroll
    for (int o = 16; o > 0; o >>= 1) m = fmaxf(m, __shfl_xor_sync(0xffffffffu, m, o));

    float e0 = expf(v.x - m), e1 = expf(v.y - m);
    float s = e0 + e1;
#pragma unroll
    for (int o = 16; o > 0; o >>= 1) s += __shfl_xor_sync(0xffffffffu, s, o);
    float inv = 1.0f / s;
    float p0 = e0 * inv, p1 = e1 * inv;

    reinterpret_cast<float2*>(out + OFF_PROBS + (size_t)token * NEXP)[lane] =
        make_float2(p0, p1);
    atomicAdd(&s_imp[2 * lane], p0);
    atomicAdd(&s_imp[2 * lane + 1], p1);

    // per-lane sorted top-2 of its two experts (tie -> lower index keeps first)
    float av, bv; int ai, bi;
    if (v.y > v.x) { av = v.y; ai = 2 * lane + 1; bv = v.x; bi = 2 * lane; }
    else           { av = v.x; ai = 2 * lane;     bv = v.y; bi = 2 * lane + 1; }

    // butterfly merge of sorted pairs
#pragma unroll
    for (int o = 16; o > 0; o >>= 1) {
        float av2 = __shfl_xor_sync(0xffffffffu, av, o);
        int   ai2 = __shfl_xor_sync(0xffffffffu, ai, o);
        float bv2 = __shfl_xor_sync(0xffffffffu, bv, o);
        int   bi2 = __shfl_xor_sync(0xffffffffu, bi, o);
        if (better(av2, ai2, av, ai)) {
            // first from other; second = best of (our first, other's second)
            bool s2 = better(bv2, bi2, av, ai);
            float nbv = s2 ? bv2 : av; int nbi = s2 ? bi2 : ai;
            av = av2; ai = ai2; bv = nbv; bi = nbi;
        } else {
            bool s2 = better(av2, ai2, bv, bi);
            if (s2) { bv = av2; bi = ai2; }
        }
    }

    if (lane == 0) {
        // renormalized top-2 softmax (av >= bv)
        float ex  = expf(bv - av);
        float sc0 = 1.0f / (1.0f + ex);
        float sc1 = ex * sc0;
        float z = m + logf(s);

        out[OFF_IDX + token * 2]        = (float)ai;
        out[OFF_IDX + token * 2 + 1]    = (float)bi;
        out[OFF_SCORES + token * 2]     = sc0;
        out[OFF_SCORES + token * 2 + 1] = sc1;

        atomicAdd(&s_cnt[ai], 1.0f);
        atomicAdd(&s_cnt[bi], 1.0f);
        atomicAdd(&s_z, z * z);
    }
    __syncthreads();

    if (tid < NEXP) {
        atomicAdd(&g_acc[tid], s_imp[tid]);
        atomicAdd(&g_acc[NEXP + tid], s_cnt[tid]);
    }
    if (tid == 0) atomicAdd(&g_acc[2 * NEXP], s_z);
}

// ---------------------------------------------------------------------------
// Kernel 4: finalize scalars
// ---------------------------------------------------------------------------
__global__ void finalize_kernel(float* __restrict__ out) {
    int t = threadIdx.x;
    if (t < NEXP) {
        out[OFF_IMP + t]  = g_acc[t] * (1.0f / (float)NTOK);
        out[OFF_LOAD + t] = g_acc[NEXP + t] * (1.0f / (float)(2 * NTOK));  // K=2 -> sum counts = 2*NTOK
    }
    if (t == 0) out[OFF_ZLOSS] = g_acc[2 * NEXP] * (1.0f / (float)NTOK);
}

// ---------------------------------------------------------------------------
extern "C" void kernel_launch(void* const* d_in, const int* in_sizes, int n_in,
                              void* d_out, int out_size) {
    const float* x = (const float*)d_in[0];       // [4,4096,4096] f32
    const float* W = (const float*)d_in[1];       // [64,4096] f32
    float* out = (float*)d_out;

    prep_kernel<<<(DDIM * NEXP + 255) / 256, 256>>>(W);
    gemm_kernel<<<NTOK / TB, 128>>>(x);
    epilogue_kernel<<<NTOK / 8, 256>>>(out);
    finalize_kernel<<<1, 64>>>(out);
}